// round 6
// baseline (speedup 1.0000x reference)
#include <cuda_runtime.h>
#include <cstdint>

// Permutation: out[b,i,j,W,p,q] = x[b, 2i+p, 2j+q, W]   (k=2 unfold repack)
// x: (16, 64, 224, 224) fp32 -> pure streaming permutation, HBM-bound.
//
// R6: TMA bulk-in (long-burst reads) + direct STG.128 out in output order.
// Each thread builds output float4s f = m*224 + tid directly from the input
// tile via 4 stride-1 conflict-free LDS -> no output staging smem, no proxy
// fence, no tail wait_group. smem 29KB -> ~14.4KB, occupancy restored.

#define W_DIM 224
#define THREADS 224
#define GRID 14336          // 57344 segments / 4

__device__ __forceinline__ uint32_t smem_u32(const void* p) {
    return (uint32_t)__cvta_generic_to_shared(p);
}

__global__ void __launch_bounds__(THREADS) KernelActivation_perm6(
    const float* __restrict__ x, float4* __restrict__ out)
{
    __shared__ __align__(16) float sin_[16 * W_DIM];  // A[8][224] | B[8][224], 14336B
    __shared__ uint64_t mbar;

    const int tid = threadIdx.x;
    const int blk = blockIdx.x;
    const int j0  = 4 * (blk % 28);     // 28 j-groups per (b,i)
    const int t   = blk / 28;
    const int i   = t & 31;
    const int b   = t >> 5;

    // x[b, 2i, 2j0, 0] : 8 h-rows x 224 floats contiguous = 7168B per channel row
    const float* srcA = x + (((b * 64 + 2 * i) * 224) + 2 * j0) * 224;
    const uint32_t mb = smem_u32(&mbar);

    if (tid == 0) {
        asm volatile("mbarrier.init.shared.b64 [%0], 1;" :: "r"(mb) : "memory");
    }
    __syncthreads();

    if (tid == 0) {
        asm volatile("mbarrier.arrive.expect_tx.shared.b64 _, [%0], %1;"
                     :: "r"(mb), "r"(14336u) : "memory");
        const uint32_t s0 = smem_u32(sin_);
        asm volatile(
            "cp.async.bulk.shared::cta.global.mbarrier::complete_tx::bytes [%0], [%1], %2, [%3];"
            :: "r"(s0), "l"(srcA), "r"(7168u), "r"(mb) : "memory");
        asm volatile(
            "cp.async.bulk.shared::cta.global.mbarrier::complete_tx::bytes [%0], [%1], %2, [%3];"
            :: "r"(s0 + 7168u), "l"(srcA + 224 * 224), "r"(7168u), "r"(mb) : "memory");
    }

    // all threads wait for both loads (phase 0)
    {
        uint32_t done;
        asm volatile(
            "{\n\t.reg .pred p;\n\t"
            "mbarrier.try_wait.parity.shared.b64 p, [%1], 0;\n\t"
            "selp.b32 %0, 1, 0, p;\n\t}"
            : "=r"(done) : "r"(mb) : "memory");
        while (!done) {
            asm volatile(
                "{\n\t.reg .pred p;\n\t"
                "mbarrier.try_wait.parity.shared.b64 p, [%1], 0, 0x989680;\n\t"
                "selp.b32 %0, 1, 0, p;\n\t}"
                : "=r"(done) : "r"(mb) : "memory");
        }
    }

    // direct output: float4 index f = m*224 + tid in the contiguous 14336B
    // output block; value = {A[2m][w], A[2m+1][w], B[2m][w], B[2m+1][w]}
    float4* dst = out + (size_t)blk * (4 * W_DIM);
#pragma unroll
    for (int m = 0; m < 4; m++) {
        const float* A = sin_ + 2 * m * W_DIM;
        float4 v;
        v.x = A[tid];                 // p=0 q=0
        v.y = A[W_DIM + tid];         // p=0 q=1
        v.z = A[8 * W_DIM + tid];     // p=1 q=0
        v.w = A[9 * W_DIM + tid];     // p=1 q=1
        __stcs(&dst[m * W_DIM + tid], v);
    }
}

extern "C" void kernel_launch(void* const* d_in, const int* in_sizes, int n_in,
                              void* d_out, int out_size)
{
    const float* x = (const float*)d_in[0];
    float4* out = (float4*)d_out;
    KernelActivation_perm6<<<GRID, THREADS>>>(x, out);
}

// round 7
// speedup vs baseline: 1.0005x; 1.0005x over previous
#include <cuda_runtime.h>
#include <cstdint>

// Permutation: out[b,i,j,W,p,q] = x[b, 2i+p, 2j+q, W]   (k=2 unfold repack)
// x: (16, 64, 224, 224) fp32 -> pure streaming permutation, HBM-bound.
//
// R7 = R5 (TMA bulk both ends, best DRAM% = longest bursts) with the smem
// footprint of R6: the 14336B input tile buffer is REUSED in place as the
// output staging buffer (input tile bytes == output block bytes).
//   1. 2x cp.async.bulk G->S (7168B each, rows c=2i / c=2i+1)
//   2. each thread lifts its 16 output floats to registers (stride-1 LDS)
//   3. __syncthreads, write back in output order (STS.128, conflict-free)
//   4. fence.proxy.async + 1x cp.async.bulk S->G of 14336B
// smem 29KB -> 14.4KB => 9 blocks/SM, tail wait_group hidden by peers.

#define W_DIM 224
#define THREADS 224
#define GRID 14336          // 57344 segments / 4

__device__ __forceinline__ uint32_t smem_u32(const void* p) {
    return (uint32_t)__cvta_generic_to_shared(p);
}

__global__ void __launch_bounds__(THREADS) KernelActivation_perm7(
    const float* __restrict__ x, float* __restrict__ out)
{
    __shared__ __align__(16) float s[16 * W_DIM];   // 14336 B, in-place reuse
    __shared__ uint64_t mbar;

    const int tid = threadIdx.x;
    const int blk = blockIdx.x;
    const int j0  = 4 * (blk % 28);     // 28 j-groups per (b,i)
    const int t   = blk / 28;
    const int i   = t & 31;
    const int b   = t >> 5;

    // x[b, 2i, 2j0, 0] : 8 h-rows x 224 floats contiguous = 7168B per c-row
    const float* srcA = x + (((b * 64 + 2 * i) * 224) + 2 * j0) * 224;
    const uint32_t mb = smem_u32(&mbar);

    if (tid == 0) {
        asm volatile("mbarrier.init.shared.b64 [%0], 1;" :: "r"(mb) : "memory");
    }
    __syncthreads();

    if (tid == 0) {
        asm volatile("mbarrier.arrive.expect_tx.shared.b64 _, [%0], %1;"
                     :: "r"(mb), "r"(14336u) : "memory");
        const uint32_t s0 = smem_u32(s);
        asm volatile(
            "cp.async.bulk.shared::cta.global.mbarrier::complete_tx::bytes [%0], [%1], %2, [%3];"
            :: "r"(s0), "l"(srcA), "r"(7168u), "r"(mb) : "memory");
        asm volatile(
            "cp.async.bulk.shared::cta.global.mbarrier::complete_tx::bytes [%0], [%1], %2, [%3];"
            :: "r"(s0 + 7168u), "l"(srcA + 224 * 224), "r"(7168u), "r"(mb) : "memory");
    }

    // wait for both loads (phase 0)
    {
        uint32_t done;
        asm volatile(
            "{\n\t.reg .pred p;\n\t"
            "mbarrier.try_wait.parity.shared.b64 p, [%1], 0;\n\t"
            "selp.b32 %0, 1, 0, p;\n\t}"
            : "=r"(done) : "r"(mb) : "memory");
        while (!done) {
            asm volatile(
                "{\n\t.reg .pred p;\n\t"
                "mbarrier.try_wait.parity.shared.b64 p, [%1], 0, 0x989680;\n\t"
                "selp.b32 %0, 1, 0, p;\n\t}"
                : "=r"(done) : "r"(mb) : "memory");
        }
    }

    // lift this thread's 16 output floats to registers:
    // out4[m*224 + tid] = {A[2m][w], A[2m+1][w], B[2m][w], B[2m+1][w]}, w=tid
    float4 v[4];
#pragma unroll
    for (int m = 0; m < 4; m++) {
        const float* A = s + 2 * m * W_DIM;
        v[m].x = A[tid];               // p=0 q=0
        v[m].y = A[W_DIM + tid];       // p=0 q=1
        v[m].z = A[8 * W_DIM + tid];   // p=1 q=0
        v[m].w = A[9 * W_DIM + tid];   // p=1 q=1
    }

    __syncthreads();   // all reads of the tile done before overwrite

    // write back in output order (in-place reuse)
    float4* s4 = (float4*)s;
#pragma unroll
    for (int m = 0; m < 4; m++) {
        s4[m * W_DIM + tid] = v[m];
    }

    asm volatile("fence.proxy.async.shared::cta;" ::: "memory");
    __syncthreads();

    if (tid == 0) {
        char* dst = (char*)out + (size_t)blk * 14336;
        asm volatile(
            "cp.async.bulk.global.shared::cta.bulk_group [%0], [%1], %2;"
            :: "l"(dst), "r"(smem_u32(s)), "r"(14336u) : "memory");
        asm volatile("cp.async.bulk.commit_group;" ::: "memory");
        asm volatile("cp.async.bulk.wait_group 0;" ::: "memory");
    }
}

extern "C" void kernel_launch(void* const* d_in, const int* in_sizes, int n_in,
                              void* d_out, int out_size)
{
    const float* x = (const float*)d_in[0];
    float* out = (float*)d_out;
    KernelActivation_perm7<<<GRID, THREADS>>>(x, out);
}